// round 2
// baseline (speedup 1.0000x reference)
#include <cuda_runtime.h>
#include <math.h>

#define B_   2
#define S_   2048
#define DM_  1024
#define NH_  16
#define NKV_ 4
#define DH_  64
#define M_   (B_*S_)   // 4096

// ---------------- scratch (device globals; no allocation allowed) ----------
__device__ float g_qt[(size_t)M_*1024];           // x @ Wq   [m][h*64+d]
__device__ float g_kt[(size_t)M_*256];            // x @ Wk
__device__ float g_vt[(size_t)M_*256];            // x @ Wv
__device__ float g_Q[(size_t)B_*NH_*S_*DH_];      // [b,h,s,d] normalized+rope
__device__ float g_K[(size_t)B_*NKV_*S_*DH_];
__device__ float g_V[(size_t)B_*NKV_*S_*DH_];
__device__ float g_ctx[(size_t)M_*1024];          // attention out [b,s,h*64+d]

// ---------------- generic fp32 GEMM: C[M,N] = A[M,K] @ B[K,N] --------------
// 128x128 block tile, 256 threads, 8x8 micro tile, K-step 8.
// Requires M%128==0, N%128==0, K%8==0.
__global__ __launch_bounds__(256) void sgemm128(const float* __restrict__ A,
                                                const float* __restrict__ Bm,
                                                float* __restrict__ C,
                                                int M, int N, int K)
{
    __shared__ float As[8][128];
    __shared__ float Bs[8][132];
    const int tid = threadIdx.x;
    const int tx = tid & 15, ty = tid >> 4;
    const int rowBase = blockIdx.y << 7;
    const int colBase = blockIdx.x << 7;
    const int arow = tid >> 1, ak = (tid & 1) << 2;
    const int bk = tid >> 5, bcol = (tid & 31) << 2;

    float acc[8][8];
#pragma unroll
    for (int i = 0; i < 8; i++)
#pragma unroll
        for (int j = 0; j < 8; j++) acc[i][j] = 0.f;

    const float* Aptr = A + (size_t)(rowBase + arow) * K + ak;
    const float* Bptr = Bm + (size_t)bk * N + colBase + bcol;

    for (int k0 = 0; k0 < K; k0 += 8) {
        float4 av = *(const float4*)(Aptr + k0);
        float4 bv = *(const float4*)(Bptr + (size_t)k0 * N);
        As[ak + 0][arow] = av.x;
        As[ak + 1][arow] = av.y;
        As[ak + 2][arow] = av.z;
        As[ak + 3][arow] = av.w;
        *(float4*)&Bs[bk][bcol] = bv;
        __syncthreads();
#pragma unroll
        for (int kk = 0; kk < 8; kk++) {
            float a[8], b[8];
            *(float4*)(a)     = *(const float4*)&As[kk][(ty << 3)];
            *(float4*)(a + 4) = *(const float4*)&As[kk][(ty << 3) + 4];
            *(float4*)(b)     = *(const float4*)&Bs[kk][(tx << 3)];
            *(float4*)(b + 4) = *(const float4*)&Bs[kk][(tx << 3) + 4];
#pragma unroll
            for (int i = 0; i < 8; i++)
#pragma unroll
                for (int j = 0; j < 8; j++)
                    acc[i][j] = fmaf(a[i], b[j], acc[i][j]);
        }
        __syncthreads();
    }

#pragma unroll
    for (int i = 0; i < 8; i++) {
        float* cp = C + (size_t)(rowBase + (ty << 3) + i) * N + colBase + (tx << 3);
        *(float4*)(cp)     = make_float4(acc[i][0], acc[i][1], acc[i][2], acc[i][3]);
        *(float4*)(cp + 4) = make_float4(acc[i][4], acc[i][5], acc[i][6], acc[i][7]);
    }
}

// ---------------- L2-normalize + RoPE + transpose to [b,h,s,d] -------------
// One warp per (row m, head-slot). slots: 0..15 Q heads, 16..19 K heads, 20..23 V heads.
__global__ __launch_bounds__(256) void normrope_kernel(const float* __restrict__ cosb,
                                                       const float* __restrict__ sinb)
{
    const int gwarp = (blockIdx.x * blockDim.x + threadIdx.x) >> 5;
    const int lane = threadIdx.x & 31;
    if (gwarp >= M_ * 24) return;
    const int slot = gwarp % 24;
    const int m = gwarp / 24;
    const int b = m / S_, s = m % S_;

    if (slot < 16) {                      // Q head
        const int h = slot;
        const float* src = g_qt + (size_t)m * 1024 + h * 64;
        float v0 = src[lane], v1 = src[lane + 32];
        float ss = v0 * v0 + v1 * v1;
#pragma unroll
        for (int o = 16; o; o >>= 1) ss += __shfl_xor_sync(0xffffffffu, ss, o);
        float inv = 1.0f / (sqrtf(ss) + 1e-8f);
        float x1 = v0 * inv, x2 = v1 * inv;
        float c = cosb[s * 32 + lane], sn = sinb[s * 32 + lane];
        float* dst = g_Q + ((size_t)(b * NH_ + h) * S_ + s) * DH_;
        dst[lane]      = x1 * c - x2 * sn;
        dst[lane + 32] = x1 * sn + x2 * c;
    } else if (slot < 20) {               // K head
        const int h = slot - 16;
        const float* src = g_kt + (size_t)m * 256 + h * 64;
        float v0 = src[lane], v1 = src[lane + 32];
        float ss = v0 * v0 + v1 * v1;
#pragma unroll
        for (int o = 16; o; o >>= 1) ss += __shfl_xor_sync(0xffffffffu, ss, o);
        float inv = 1.0f / (sqrtf(ss) + 1e-8f);
        float x1 = v0 * inv, x2 = v1 * inv;
        float c = cosb[s * 32 + lane], sn = sinb[s * 32 + lane];
        float* dst = g_K + ((size_t)(b * NKV_ + h) * S_ + s) * DH_;
        dst[lane]      = x1 * c - x2 * sn;
        dst[lane + 32] = x1 * sn + x2 * c;
    } else {                              // V head (plain transpose)
        const int h = slot - 20;
        const float* src = g_vt + (size_t)m * 256 + h * 64;
        float* dst = g_V + ((size_t)(b * NKV_ + h) * S_ + s) * DH_;
        dst[lane]      = src[lane];
        dst[lane + 32] = src[lane + 32];
    }
}

// ---------------- attention --------------------------------------------------
__device__ __forceinline__ float fast_tanh(float x)
{
    float y;
    asm("tanh.approx.f32 %0, %1;" : "=f"(y) : "f"(x));
    return y;
}

#define PAD 68
// grid: (S/64, NH, B); block 256 (16x16 threads, 4x4 micro). dyn smem 4*64*PAD floats.
__global__ __launch_bounds__(256) void attn_kernel()
{
    extern __shared__ float sm[];
    float* Qs = sm;                 // [d][r]   transposed
    float* Ks = sm + 64 * PAD;      // [d][j]   transposed
    float* Vs = sm + 2 * 64 * PAD;  // [j][dv]
    float* Ps = sm + 3 * 64 * PAD;  // [j][r]   transposed

    const int qt = blockIdx.x, h = blockIdx.y, b = blockIdx.z;
    const int qs = qt << 6;
    const int tid = threadIdx.x;
    const int tx = tid & 15, ty = tid >> 4;
    const int hk = h >> 2;

    const float* Qg = g_Q + (size_t)(b * NH_ + h) * S_ * DH_;
    const float* Kg = g_K + (size_t)(b * NKV_ + hk) * S_ * DH_;
    const float* Vg = g_V + (size_t)(b * NKV_ + hk) * S_ * DH_;

    // load Q tile transposed
    {
        const int r = tid >> 2, dg = (tid & 3) << 4;
        const float* src = Qg + (size_t)(qs + r) * DH_ + dg;
#pragma unroll
        for (int i = 0; i < 4; i++) {
            float4 v = *(const float4*)(src + i * 4);
            const int d = dg + i * 4;
            Qs[(d + 0) * PAD + r] = v.x;
            Qs[(d + 1) * PAD + r] = v.y;
            Qs[(d + 2) * PAD + r] = v.z;
            Qs[(d + 3) * PAD + r] = v.w;
        }
    }

    float m_i[4], l_i[4], acc[4][4];
#pragma unroll
    for (int i = 0; i < 4; i++) {
        m_i[i] = -1e30f;
        l_i[i] = 0.f;
#pragma unroll
        for (int j = 0; j < 4; j++) acc[i][j] = 0.f;
    }

    const int t_lo = (qs > 255) ? ((qs - 255) >> 6) : 0;
    const int extra = (t_lo > 0) ? 1 : 0;
    const int ntiles = (qt - t_lo + 1) + extra;

    for (int it = 0; it < ntiles; it++) {
        const int kt = (extra && it == 0) ? 0 : (t_lo + it - extra);
        const int ks = kt << 6;
        __syncthreads();   // previous iteration's reads of Ks/Vs/Ps done
        {
            const int r = tid >> 2, dg = (tid & 3) << 4;
            const float* ksrc = Kg + (size_t)(ks + r) * DH_ + dg;
            const float* vsrc = Vg + (size_t)(ks + r) * DH_ + dg;
#pragma unroll
            for (int i = 0; i < 4; i++) {
                float4 v = *(const float4*)(ksrc + i * 4);
                const int d = dg + i * 4;
                Ks[(d + 0) * PAD + r] = v.x;
                Ks[(d + 1) * PAD + r] = v.y;
                Ks[(d + 2) * PAD + r] = v.z;
                Ks[(d + 3) * PAD + r] = v.w;
                *(float4*)&Vs[r * PAD + dg + i * 4] = *(const float4*)(vsrc + i * 4);
            }
        }
        __syncthreads();

        // scores: S = Q @ K^T  (64x64 via 16x16 threads, 4x4 each)
        float s[4][4];
#pragma unroll
        for (int i = 0; i < 4; i++)
#pragma unroll
            for (int j = 0; j < 4; j++) s[i][j] = 0.f;
#pragma unroll 8
        for (int d = 0; d < 64; d++) {
            float a[4], bq[4];
            *(float4*)a  = *(const float4*)&Qs[d * PAD + (ty << 2)];
            *(float4*)bq = *(const float4*)&Ks[d * PAD + (tx << 2)];
#pragma unroll
            for (int i = 0; i < 4; i++)
#pragma unroll
                for (int j = 0; j < 4; j++)
                    s[i][j] = fmaf(a[i], bq[j], s[i][j]);
        }

        // softcap + mask + online softmax
        float p[4][4];
#pragma unroll
        for (int i = 0; i < 4; i++) {
            const int row = qs + (ty << 2) + i;
            float tm = -1e30f;
#pragma unroll
            for (int j = 0; j < 4; j++) {
                const int key = ks + (tx << 2) + j;
                const bool valid = (key <= row) && ((key > row - 256) || (key < 4));
                float v = valid ? 15.0f * fast_tanh(s[i][j] * (0.125f / 15.0f)) : -1e9f;
                p[i][j] = v;
                tm = fmaxf(tm, v);
            }
#pragma unroll
            for (int o = 8; o; o >>= 1)
                tm = fmaxf(tm, __shfl_xor_sync(0xffffffffu, tm, o, 16));
            const float nm = fmaxf(m_i[i], tm);
            const float f = __expf(m_i[i] - nm);
            m_i[i] = nm;
            float rs = 0.f;
#pragma unroll
            for (int j = 0; j < 4; j++) {
                p[i][j] = __expf(p[i][j] - nm);
                rs += p[i][j];
            }
#pragma unroll
            for (int o = 8; o; o >>= 1)
                rs += __shfl_xor_sync(0xffffffffu, rs, o, 16);
            l_i[i] = l_i[i] * f + rs;
#pragma unroll
            for (int j = 0; j < 4; j++) acc[i][j] *= f;
        }

        // write P transposed [key][row]
#pragma unroll
        for (int j = 0; j < 4; j++)
#pragma unroll
            for (int i = 0; i < 4; i++)
                Ps[((tx << 2) + j) * PAD + (ty << 2) + i] = p[i][j];
        __syncthreads();

        // acc += P @ V
#pragma unroll 8
        for (int kk = 0; kk < 64; kk++) {
            float a[4], bv[4];
            *(float4*)a  = *(const float4*)&Ps[kk * PAD + (ty << 2)];
            *(float4*)bv = *(const float4*)&Vs[kk * PAD + (tx << 2)];
#pragma unroll
            for (int i = 0; i < 4; i++)
#pragma unroll
                for (int j = 0; j < 4; j++)
                    acc[i][j] = fmaf(a[i], bv[j], acc[i][j]);
        }
    }

    // epilogue: ctx[b, row, h*64 + dv] = acc / l
#pragma unroll
    for (int i = 0; i < 4; i++) {
        const float inv = 1.0f / l_i[i];
        const int row = qs + (ty << 2) + i;
        float* cp = g_ctx + (size_t)(b * S_ + row) * 1024 + h * 64 + (tx << 2);
        *(float4*)cp = make_float4(acc[i][0] * inv, acc[i][1] * inv,
                                   acc[i][2] * inv, acc[i][3] * inv);
    }
}

// ---------------- launch -----------------------------------------------------
extern "C" void kernel_launch(void* const* d_in, const int* in_sizes, int n_in,
                              void* d_out, int out_size)
{
    const float* x    = (const float*)d_in[0];
    const float* cosb = (const float*)d_in[1];
    const float* sinb = (const float*)d_in[2];
    // d_in[3] = mask (pure causal) — recomputed analytically in-kernel
    const float* Wq   = (const float*)d_in[4];
    const float* Wk   = (const float*)d_in[5];
    const float* Wv   = (const float*)d_in[6];
    const float* Wo   = (const float*)d_in[7];
    float* out = (float*)d_out;

    float *qt, *kt, *vt, *ctx;
    cudaGetSymbolAddress((void**)&qt,  g_qt);
    cudaGetSymbolAddress((void**)&kt,  g_kt);
    cudaGetSymbolAddress((void**)&vt,  g_vt);
    cudaGetSymbolAddress((void**)&ctx, g_ctx);

    const dim3 blk(256);
    // QKV projections
    sgemm128<<<dim3(1024 / 128, M_ / 128), blk>>>(x, Wq, qt, M_, 1024, 1024);
    sgemm128<<<dim3(256 / 128,  M_ / 128), blk>>>(x, Wk, kt, M_, 256, 1024);
    sgemm128<<<dim3(256 / 128,  M_ / 128), blk>>>(x, Wv, vt, M_, 256, 1024);

    // normalize + rope + layout transform
    normrope_kernel<<<(M_ * 24) / 8, 256>>>(cosb, sinb);

    // attention
    const int smem = 4 * 64 * PAD * (int)sizeof(float);
    cudaFuncSetAttribute(attn_kernel, cudaFuncAttributeMaxDynamicSharedMemorySize, smem);
    attn_kernel<<<dim3(S_ / 64, NH_, B_), blk, smem>>>();

    // output projection
    sgemm128<<<dim3(1024 / 128, M_ / 128), blk>>>(ctx, Wo, out, M_, 1024, 1024);
}

// round 5
// speedup vs baseline: 2.4641x; 2.4641x over previous
#include <cuda_runtime.h>
#include <cstdint>
#include <math.h>

#define B_   2
#define S_   2048
#define DM_  1024
#define NH_  16
#define NKV_ 4
#define DH_  64
#define M_   (B_*S_)   // 4096

// ---------------- scratch (device globals; no allocation allowed) ----------
__device__ float g_qkv[(size_t)M_*1536];          // fused [m][1536]: q 0..1023, k 1024..1279, v 1280..1535
__device__ float g_Q[(size_t)B_*NH_*S_*DH_];
__device__ float g_K[(size_t)B_*NKV_*S_*DH_];
__device__ float g_V[(size_t)B_*NKV_*S_*DH_];
__device__ float g_ctx[(size_t)M_*1024];
__device__ float g_WqkvT[(size_t)1536*1024];      // [N][K] tf32-rounded, fused
__device__ float g_WoT[(size_t)1024*1024];

__device__ __forceinline__ float to_tf32(float x) {
    float y;
    asm("cvt.rna.tf32.f32 %0, %1;" : "=f"(y) : "f"(x));
    return y;
}

// ---------------- weight transpose + tf32 round: W[K,N] -> WT[N,K] ----------
__global__ __launch_bounds__(256) void wtrans(const float* __restrict__ W,
                                              float* __restrict__ WT, int Kdim, int Ndim)
{
    __shared__ float t[32][33];
    const int n0 = blockIdx.x * 32, k0 = blockIdx.y * 32;
    const int tx = threadIdx.x, ty = threadIdx.y;   // 32 x 8
#pragma unroll
    for (int i = 0; i < 32; i += 8)
        t[ty + i][tx] = W[(size_t)(k0 + ty + i) * Ndim + n0 + tx];
    __syncthreads();
#pragma unroll
    for (int i = 0; i < 32; i += 8)
        WT[(size_t)(n0 + ty + i) * Kdim + k0 + tx] = to_tf32(t[tx][ty + i]);
}

// ---------------- tf32 mma.sync GEMM: C[M,N] = A[M,K] @ BT[N,K]^T -----------
// 128x128 block tile, 256 threads = 8 warps (4 m x 2 n), warp tile 32x64.
// m16n8k8 HMMA, K-chunk 32 staged in smem with stride-36 padding (conflict-free).
#define KP 36
__global__ __launch_bounds__(256) void tgemm(const float* __restrict__ A,
                                             const float* __restrict__ BT,
                                             float* __restrict__ C,
                                             int Ndim, int Kdim)
{
    __shared__ float As[128][KP];
    __shared__ float Bs[128][KP];

    const int tid = threadIdx.x;
    const int wid = tid >> 5, lane = tid & 31;
    const int g = lane >> 2, tg = lane & 3;          // groupID, thread-in-group
    const int wm = wid & 3, wn = wid >> 2;           // warp 32-row slab, 64-col slab
    const int rowBase = blockIdx.y << 7;
    const int colBase = blockIdx.x << 7;

    float c[2][8][4];
#pragma unroll
    for (int mt = 0; mt < 2; mt++)
#pragma unroll
        for (int nt = 0; nt < 8; nt++)
#pragma unroll
            for (int r = 0; r < 4; r++) c[mt][nt][r] = 0.f;

    const int nchunk = Kdim >> 5;
    for (int ch = 0; ch < nchunk; ch++) {
        __syncthreads();
        // stage A (tf32-round) and B tiles: 128 rows x 32 k
#pragma unroll
        for (int i = 0; i < 4; i++) {
            const int p = tid + (i << 8);            // 0..1023
            const int r = p >> 3, j = (p & 7) << 2;
            float4 av = *(const float4*)(A + (size_t)(rowBase + r) * Kdim + (ch << 5) + j);
            av.x = to_tf32(av.x); av.y = to_tf32(av.y);
            av.z = to_tf32(av.z); av.w = to_tf32(av.w);
            *(float4*)&As[r][j] = av;
            *(float4*)&Bs[r][j] = *(const float4*)(BT + (size_t)(colBase + r) * Kdim + (ch << 5) + j);
        }
        __syncthreads();

        const uint32_t* As32 = (const uint32_t*)&As[0][0];
        const uint32_t* Bs32 = (const uint32_t*)&Bs[0][0];
#pragma unroll
        for (int ks = 0; ks < 4; ks++) {
            const int kk = ks << 3;
            uint32_t a[2][4], b[8][2];
#pragma unroll
            for (int mt = 0; mt < 2; mt++) {
                const int rA = ((wm << 5) + (mt << 4) + g) * KP + kk + tg;
                a[mt][0] = As32[rA];
                a[mt][1] = As32[rA + 8 * KP];
                a[mt][2] = As32[rA + 4];
                a[mt][3] = As32[rA + 8 * KP + 4];
            }
#pragma unroll
            for (int nt = 0; nt < 8; nt++) {
                const int rB = ((wn << 6) + (nt << 3) + g) * KP + kk + tg;
                b[nt][0] = Bs32[rB];
                b[nt][1] = Bs32[rB + 4];
            }
#pragma unroll
            for (int mt = 0; mt < 2; mt++)
#pragma unroll
                for (int nt = 0; nt < 8; nt++)
                    asm volatile(
                        "mma.sync.aligned.m16n8k8.row.col.f32.tf32.tf32.f32 "
                        "{%0,%1,%2,%3}, {%4,%5,%6,%7}, {%8,%9}, {%0,%1,%2,%3};"
                        : "+f"(c[mt][nt][0]), "+f"(c[mt][nt][1]),
                          "+f"(c[mt][nt][2]), "+f"(c[mt][nt][3])
                        : "r"(a[mt][0]), "r"(a[mt][1]), "r"(a[mt][2]), "r"(a[mt][3]),
                          "r"(b[nt][0]), "r"(b[nt][1]));
        }
    }

    // epilogue
#pragma unroll
    for (int mt = 0; mt < 2; mt++) {
        const int row0 = rowBase + (wm << 5) + (mt << 4) + g;
#pragma unroll
        for (int nt = 0; nt < 8; nt++) {
            const int col = colBase + (wn << 6) + (nt << 3) + (tg << 1);
            *(float2*)(C + (size_t)row0 * Ndim + col)       = make_float2(c[mt][nt][0], c[mt][nt][1]);
            *(float2*)(C + (size_t)(row0 + 8) * Ndim + col) = make_float2(c[mt][nt][2], c[mt][nt][3]);
        }
    }
}

// ---------------- L2-normalize + RoPE + transpose to [b,h,s,d] -------------
__global__ __launch_bounds__(256) void normrope_kernel(const float* __restrict__ cosb,
                                                       const float* __restrict__ sinb)
{
    const int gwarp = (blockIdx.x * blockDim.x + threadIdx.x) >> 5;
    const int lane = threadIdx.x & 31;
    if (gwarp >= M_ * 24) return;
    const int slot = gwarp % 24;
    const int m = gwarp / 24;
    const int b = m / S_, s = m % S_;

    if (slot < 16) {
        const int h = slot;
        const float* src = g_qkv + (size_t)m * 1536 + h * 64;
        float v0 = src[lane], v1 = src[lane + 32];
        float ss = v0 * v0 + v1 * v1;
#pragma unroll
        for (int o = 16; o; o >>= 1) ss += __shfl_xor_sync(0xffffffffu, ss, o);
        float inv = 1.0f / (sqrtf(ss) + 1e-8f);
        float x1 = v0 * inv, x2 = v1 * inv;
        float cc = cosb[s * 32 + lane], sn = sinb[s * 32 + lane];
        float* dst = g_Q + ((size_t)(b * NH_ + h) * S_ + s) * DH_;
        dst[lane]      = x1 * cc - x2 * sn;
        dst[lane + 32] = x1 * sn + x2 * cc;
    } else if (slot < 20) {
        const int h = slot - 16;
        const float* src = g_qkv + (size_t)m * 1536 + 1024 + h * 64;
        float v0 = src[lane], v1 = src[lane + 32];
        float ss = v0 * v0 + v1 * v1;
#pragma unroll
        for (int o = 16; o; o >>= 1) ss += __shfl_xor_sync(0xffffffffu, ss, o);
        float inv = 1.0f / (sqrtf(ss) + 1e-8f);
        float x1 = v0 * inv, x2 = v1 * inv;
        float cc = cosb[s * 32 + lane], sn = sinb[s * 32 + lane];
        float* dst = g_K + ((size_t)(b * NKV_ + h) * S_ + s) * DH_;
        dst[lane]      = x1 * cc - x2 * sn;
        dst[lane + 32] = x1 * sn + x2 * cc;
    } else {
        const int h = slot - 20;
        const float* src = g_qkv + (size_t)m * 1536 + 1280 + h * 64;
        float* dst = g_V + ((size_t)(b * NKV_ + h) * S_ + s) * DH_;
        dst[lane]      = src[lane];
        dst[lane + 32] = src[lane + 32];
    }
}

// ---------------- attention --------------------------------------------------
__device__ __forceinline__ float fast_tanh(float x)
{
    float y;
    asm("tanh.approx.f32 %0, %1;" : "=f"(y) : "f"(x));
    return y;
}

#define PAD 68
__global__ __launch_bounds__(256) void attn_kernel()
{
    extern __shared__ float sm[];
    float* Qs = sm;
    float* Ks = sm + 64 * PAD;
    float* Vs = sm + 2 * 64 * PAD;
    float* Ps = sm + 3 * 64 * PAD;

    const int qt = blockIdx.x, h = blockIdx.y, b = blockIdx.z;
    const int qs = qt << 6;
    const int tid = threadIdx.x;
    const int tx = tid & 15, ty = tid >> 4;
    const int hk = h >> 2;

    const float* Qg = g_Q + (size_t)(b * NH_ + h) * S_ * DH_;
    const float* Kg = g_K + (size_t)(b * NKV_ + hk) * S_ * DH_;
    const float* Vg = g_V + (size_t)(b * NKV_ + hk) * S_ * DH_;

    {
        const int r = tid >> 2, dg = (tid & 3) << 4;
        const float* src = Qg + (size_t)(qs + r) * DH_ + dg;
#pragma unroll
        for (int i = 0; i < 4; i++) {
            float4 v = *(const float4*)(src + i * 4);
            const int d = dg + i * 4;
            Qs[(d + 0) * PAD + r] = v.x;
            Qs[(d + 1) * PAD + r] = v.y;
            Qs[(d + 2) * PAD + r] = v.z;
            Qs[(d + 3) * PAD + r] = v.w;
        }
    }

    float m_i[4], l_i[4], acc[4][4];
#pragma unroll
    for (int i = 0; i < 4; i++) {
        m_i[i] = -1e30f;
        l_i[i] = 0.f;
#pragma unroll
        for (int j = 0; j < 4; j++) acc[i][j] = 0.f;
    }

    const int t_lo = (qs > 255) ? ((qs - 255) >> 6) : 0;
    const int extra = (t_lo > 0) ? 1 : 0;
    const int ntiles = (qt - t_lo + 1) + extra;

    for (int it = 0; it < ntiles; it++) {
        const int kt = (extra && it == 0) ? 0 : (t_lo + it - extra);
        const int ks = kt << 6;
        __syncthreads();
        {
            const int r = tid >> 2, dg = (tid & 3) << 4;
            const float* ksrc = Kg + (size_t)(ks + r) * DH_ + dg;
            const float* vsrc = Vg + (size_t)(ks + r) * DH_ + dg;
#pragma unroll
            for (int i = 0; i < 4; i++) {
                float4 v = *(const float4*)(ksrc + i * 4);
                const int d = dg + i * 4;
                Ks[(d + 0) * PAD + r] = v.x;
                Ks[(d + 1) * PAD + r] = v.y;
                Ks[(d + 2) * PAD + r] = v.z;
                Ks[(d + 3) * PAD + r] = v.w;
                *(float4*)&Vs[r * PAD + dg + i * 4] = *(const float4*)(vsrc + i * 4);
            }
        }
        __syncthreads();

        float s[4][4];
#pragma unroll
        for (int i = 0; i < 4; i++)
#pragma unroll
            for (int j = 0; j < 4; j++) s[i][j] = 0.f;
#pragma unroll 8
        for (int d = 0; d < 64; d++) {
            float a[4], bq[4];
            *(float4*)a  = *(const float4*)&Qs[d * PAD + (ty << 2)];
            *(float4*)bq = *(const float4*)&Ks[d * PAD + (tx << 2)];
#pragma unroll
            for (int i = 0; i < 4; i++)
#pragma unroll
                for (int j = 0; j < 4; j++)
                    s[i][j] = fmaf(a[i], bq[j], s[i][j]);
        }

        float p[4][4];
#pragma unroll
        for (int i = 0; i < 4; i++) {
            const int row = qs + (ty << 2) + i;
            float tm = -1e30f;
#pragma unroll
            for (int j = 0; j < 4; j++) {
                const int key = ks + (tx << 2) + j;
                const bool valid = (key <= row) && ((key > row - 256) || (key < 4));
                float v = valid ? 15.0f * fast_tanh(s[i][j] * (0.125f / 15.0f)) : -1e9f;
                p[i][j] = v;
                tm = fmaxf(tm, v);
            }
#pragma unroll
            for (int o = 8; o; o >>= 1)
                tm = fmaxf(tm, __shfl_xor_sync(0xffffffffu, tm, o, 16));
            const float nm = fmaxf(m_i[i], tm);
            const float f = __expf(m_i[i] - nm);
            m_i[i] = nm;
            float rs = 0.f;
#pragma unroll
            for (int j = 0; j < 4; j++) {
                p[i][j] = __expf(p[i][j] - nm);
                rs += p[i][j];
            }
#pragma unroll
            for (int o = 8; o; o >>= 1)
                rs += __shfl_xor_sync(0xffffffffu, rs, o, 16);
            l_i[i] = l_i[i] * f + rs;
#pragma unroll
            for (int j = 0; j < 4; j++) acc[i][j] *= f;
        }

#pragma unroll
        for (int j = 0; j < 4; j++)
#pragma unroll
            for (int i = 0; i < 4; i++)
                Ps[((tx << 2) + j) * PAD + (ty << 2) + i] = p[i][j];
        __syncthreads();

#pragma unroll 8
        for (int kk = 0; kk < 64; kk++) {
            float a[4], bv[4];
            *(float4*)a  = *(const float4*)&Ps[kk * PAD + (ty << 2)];
            *(float4*)bv = *(const float4*)&Vs[kk * PAD + (tx << 2)];
#pragma unroll
            for (int i = 0; i < 4; i++)
#pragma unroll
                for (int j = 0; j < 4; j++)
                    acc[i][j] = fmaf(a[i], bv[j], acc[i][j]);
        }
    }

#pragma unroll
    for (int i = 0; i < 4; i++) {
        const float inv = 1.0f / l_i[i];
        const int row = qs + (ty << 2) + i;
        float* cp = g_ctx + (size_t)(b * S_ + row) * 1024 + h * 64 + (tx << 2);
        *(float4*)cp = make_float4(acc[i][0] * inv, acc[i][1] * inv,
                                   acc[i][2] * inv, acc[i][3] * inv);
    }
}

// ---------------- launch -----------------------------------------------------
extern "C" void kernel_launch(void* const* d_in, const int* in_sizes, int n_in,
                              void* d_out, int out_size)
{
    const float* x    = (const float*)d_in[0];
    const float* cosb = (const float*)d_in[1];
    const float* sinb = (const float*)d_in[2];
    const float* Wq   = (const float*)d_in[4];
    const float* Wk   = (const float*)d_in[5];
    const float* Wv   = (const float*)d_in[6];
    const float* Wo   = (const float*)d_in[7];
    float* out = (float*)d_out;

    float *qkv, *ctx, *wqkvT, *woT;
    cudaGetSymbolAddress((void**)&qkv,   g_qkv);
    cudaGetSymbolAddress((void**)&ctx,   g_ctx);
    cudaGetSymbolAddress((void**)&wqkvT, g_WqkvT);
    cudaGetSymbolAddress((void**)&woT,   g_WoT);

    // weight transposes (+ tf32 rounding) into fused [1536][1024]
    wtrans<<<dim3(32, 32), dim3(32, 8)>>>(Wq, wqkvT,                       1024, 1024);
    wtrans<<<dim3(8,  32), dim3(32, 8)>>>(Wk, wqkvT + (size_t)1024 * 1024, 1024, 256);
    wtrans<<<dim3(8,  32), dim3(32, 8)>>>(Wv, wqkvT + (size_t)1280 * 1024, 1024, 256);
    wtrans<<<dim3(32, 32), dim3(32, 8)>>>(Wo, woT,                         1024, 1024);

    // fused QKV projection (tf32 mma.sync)
    tgemm<<<dim3(12, 32), 256>>>(x, wqkvT, qkv, 1536, 1024);

    normrope_kernel<<<(M_ * 24) / 8, 256>>>(cosb, sinb);

    const int smem = 4 * 64 * PAD * (int)sizeof(float);
    cudaFuncSetAttribute(attn_kernel, cudaFuncAttributeMaxDynamicSharedMemorySize, smem);
    attn_kernel<<<dim3(S_ / 64, NH_, B_), 256, smem>>>();

    // output projection (tf32 mma.sync)
    tgemm<<<dim3(8, 32), 256>>>(ctx, woT, out, 1024, 1024);
}

// round 6
// speedup vs baseline: 3.1119x; 1.2629x over previous
#include <cuda_runtime.h>
#include <cstdint>
#include <math.h>

#define B_   2
#define S_   2048
#define DM_  1024
#define NH_  16
#define NKV_ 4
#define DH_  64
#define M_   (B_*S_)   // 4096

// ---------------- scratch (device globals; no allocation allowed) ----------
__device__ float g_qkv[(size_t)M_*1536];          // fused [m][1536]
__device__ float g_Q[(size_t)B_*NH_*S_*DH_];
__device__ float g_K[(size_t)B_*NKV_*S_*DH_];
__device__ float g_V[(size_t)B_*NKV_*S_*DH_];
__device__ float g_ctx[(size_t)M_*1024];
__device__ float g_WqkvT[(size_t)1536*1024];      // [N][K] tf32-rounded, fused
__device__ float g_WoT[(size_t)1024*1024];

__device__ __forceinline__ float to_tf32(float x) {
    float y;
    asm("cvt.rna.tf32.f32 %0, %1;" : "=f"(y) : "f"(x));
    return y;
}

#define MMA_TF32(c0,c1,c2,c3,a0,a1,a2,a3,b0,b1) \
    asm volatile("mma.sync.aligned.m16n8k8.row.col.f32.tf32.tf32.f32 " \
        "{%0,%1,%2,%3}, {%4,%5,%6,%7}, {%8,%9}, {%0,%1,%2,%3};" \
        : "+f"(c0), "+f"(c1), "+f"(c2), "+f"(c3) \
        : "r"(a0), "r"(a1), "r"(a2), "r"(a3), "r"(b0), "r"(b1))

// ---------------- weight transpose + tf32 round: W[K,N] -> WT[N,K] ----------
__global__ __launch_bounds__(256) void wtrans(const float* __restrict__ W,
                                              float* __restrict__ WT, int Kdim, int Ndim)
{
    __shared__ float t[32][33];
    const int n0 = blockIdx.x * 32, k0 = blockIdx.y * 32;
    const int tx = threadIdx.x, ty = threadIdx.y;   // 32 x 8
#pragma unroll
    for (int i = 0; i < 32; i += 8)
        t[ty + i][tx] = W[(size_t)(k0 + ty + i) * Ndim + n0 + tx];
    __syncthreads();
#pragma unroll
    for (int i = 0; i < 32; i += 8)
        WT[(size_t)(n0 + ty + i) * Kdim + k0 + tx] = to_tf32(t[tx][ty + i]);
}

// ---------------- tf32 mma.sync GEMM: C[M,N] = A[M,K] @ BT[N,K]^T -----------
#define KP 36
__global__ __launch_bounds__(256) void tgemm(const float* __restrict__ A,
                                             const float* __restrict__ BT,
                                             float* __restrict__ C,
                                             int Ndim, int Kdim)
{
    __shared__ float As[128][KP];
    __shared__ float Bs[128][KP];

    const int tid = threadIdx.x;
    const int wid = tid >> 5, lane = tid & 31;
    const int g = lane >> 2, tg = lane & 3;
    const int wm = wid & 3, wn = wid >> 2;
    const int rowBase = blockIdx.y << 7;
    const int colBase = blockIdx.x << 7;

    float c[2][8][4];
#pragma unroll
    for (int mt = 0; mt < 2; mt++)
#pragma unroll
        for (int nt = 0; nt < 8; nt++)
#pragma unroll
            for (int r = 0; r < 4; r++) c[mt][nt][r] = 0.f;

    const int nchunk = Kdim >> 5;
    for (int ch = 0; ch < nchunk; ch++) {
        __syncthreads();
#pragma unroll
        for (int i = 0; i < 4; i++) {
            const int p = tid + (i << 8);
            const int r = p >> 3, j = (p & 7) << 2;
            float4 av = *(const float4*)(A + (size_t)(rowBase + r) * Kdim + (ch << 5) + j);
            av.x = to_tf32(av.x); av.y = to_tf32(av.y);
            av.z = to_tf32(av.z); av.w = to_tf32(av.w);
            *(float4*)&As[r][j] = av;
            *(float4*)&Bs[r][j] = *(const float4*)(BT + (size_t)(colBase + r) * Kdim + (ch << 5) + j);
        }
        __syncthreads();

        const uint32_t* As32 = (const uint32_t*)&As[0][0];
        const uint32_t* Bs32 = (const uint32_t*)&Bs[0][0];
#pragma unroll
        for (int ks = 0; ks < 4; ks++) {
            const int kk = ks << 3;
            uint32_t a[2][4], b[8][2];
#pragma unroll
            for (int mt = 0; mt < 2; mt++) {
                const int rA = ((wm << 5) + (mt << 4) + g) * KP + kk + tg;
                a[mt][0] = As32[rA];
                a[mt][1] = As32[rA + 8 * KP];
                a[mt][2] = As32[rA + 4];
                a[mt][3] = As32[rA + 8 * KP + 4];
            }
#pragma unroll
            for (int nt = 0; nt < 8; nt++) {
                const int rB = ((wn << 6) + (nt << 3) + g) * KP + kk + tg;
                b[nt][0] = Bs32[rB];
                b[nt][1] = Bs32[rB + 4];
            }
#pragma unroll
            for (int mt = 0; mt < 2; mt++)
#pragma unroll
                for (int nt = 0; nt < 8; nt++)
                    MMA_TF32(c[mt][nt][0], c[mt][nt][1], c[mt][nt][2], c[mt][nt][3],
                             a[mt][0], a[mt][1], a[mt][2], a[mt][3],
                             b[nt][0], b[nt][1]);
        }
    }

#pragma unroll
    for (int mt = 0; mt < 2; mt++) {
        const int row0 = rowBase + (wm << 5) + (mt << 4) + g;
#pragma unroll
        for (int nt = 0; nt < 8; nt++) {
            const int col = colBase + (wn << 6) + (nt << 3) + (tg << 1);
            *(float2*)(C + (size_t)row0 * Ndim + col)       = make_float2(c[mt][nt][0], c[mt][nt][1]);
            *(float2*)(C + (size_t)(row0 + 8) * Ndim + col) = make_float2(c[mt][nt][2], c[mt][nt][3]);
        }
    }
}

// ---------------- L2-normalize + RoPE + transpose to [b,h,s,d] -------------
__global__ __launch_bounds__(256) void normrope_kernel(const float* __restrict__ cosb,
                                                       const float* __restrict__ sinb)
{
    const int gwarp = (blockIdx.x * blockDim.x + threadIdx.x) >> 5;
    const int lane = threadIdx.x & 31;
    if (gwarp >= M_ * 24) return;
    const int slot = gwarp % 24;
    const int m = gwarp / 24;
    const int b = m / S_, s = m % S_;

    if (slot < 16) {
        const int h = slot;
        const float* src = g_qkv + (size_t)m * 1536 + h * 64;
        float v0 = src[lane], v1 = src[lane + 32];
        float ss = v0 * v0 + v1 * v1;
#pragma unroll
        for (int o = 16; o; o >>= 1) ss += __shfl_xor_sync(0xffffffffu, ss, o);
        float inv = 1.0f / (sqrtf(ss) + 1e-8f);
        float x1 = v0 * inv, x2 = v1 * inv;
        float cc = cosb[s * 32 + lane], sn = sinb[s * 32 + lane];
        float* dst = g_Q + ((size_t)(b * NH_ + h) * S_ + s) * DH_;
        dst[lane]      = x1 * cc - x2 * sn;
        dst[lane + 32] = x1 * sn + x2 * cc;
    } else if (slot < 20) {
        const int h = slot - 16;
        const float* src = g_qkv + (size_t)m * 1536 + 1024 + h * 64;
        float v0 = src[lane], v1 = src[lane + 32];
        float ss = v0 * v0 + v1 * v1;
#pragma unroll
        for (int o = 16; o; o >>= 1) ss += __shfl_xor_sync(0xffffffffu, ss, o);
        float inv = 1.0f / (sqrtf(ss) + 1e-8f);
        float x1 = v0 * inv, x2 = v1 * inv;
        float cc = cosb[s * 32 + lane], sn = sinb[s * 32 + lane];
        float* dst = g_K + ((size_t)(b * NKV_ + h) * S_ + s) * DH_;
        dst[lane]      = x1 * cc - x2 * sn;
        dst[lane + 32] = x1 * sn + x2 * cc;
    } else {
        const int h = slot - 20;
        const float* src = g_qkv + (size_t)m * 1536 + 1280 + h * 64;
        float* dst = g_V + ((size_t)(b * NKV_ + h) * S_ + s) * DH_;
        dst[lane]      = src[lane];
        dst[lane + 32] = src[lane + 32];
    }
}

// ---------------- tensor-core attention -------------------------------------
// Block: 64 queries x 1 head. 128 threads = 4 warps, warp = 16 query rows.
// S = Q K^T and O += P V via m16n8k8 tf32 mma.sync.
// Softcap+exp by polynomial (logits bounded by q,k unit norm * 0.125):
//   15*tanh(s/15) = s - s^3/675 (+O(1e-10)); exp(u), |u|<=0.126, deg-4 Horner.
// Fixed-max softmax (m=0): exp in [0.88,1.13], masked -> p=0 exactly.
#define AP 68
__global__ __launch_bounds__(128) void attn_kernel()
{
    extern __shared__ float sm[];
    float* Qs = sm;                 // [64 q][AP]  (tf32)
    float* Ks = sm + 64 * AP;       // [64 k][AP]  (tf32)
    float* Vt = sm + 2 * 64 * AP;   // [64 d][AP keys] (tf32, transposed)
    float* Ps = sm + 3 * 64 * AP;   // [64 q][AP keys]

    const int qt = blockIdx.x, h = blockIdx.y, b = blockIdx.z;
    const int qs = qt << 6;
    const int tid = threadIdx.x;
    const int wid = tid >> 5, lane = tid & 31;
    const int g = lane >> 2, tg = lane & 3;
    const int hk = h >> 2;

    const float* Qg = g_Q + (size_t)(b * NH_ + h) * S_ * DH_;
    const float* Kg = g_K + (size_t)(b * NKV_ + hk) * S_ * DH_;
    const float* Vg = g_V + (size_t)(b * NKV_ + hk) * S_ * DH_;

    // stage Q (tf32-rounded): 128 threads, 2 threads/row, 32 cols each
    {
        const int r = tid >> 1, c0 = (tid & 1) << 5;
        const float* src = Qg + (size_t)(qs + r) * DH_ + c0;
#pragma unroll
        for (int i = 0; i < 8; i++) {
            float4 v = *(const float4*)(src + i * 4);
            v.x = to_tf32(v.x); v.y = to_tf32(v.y);
            v.z = to_tf32(v.z); v.w = to_tf32(v.w);
            *(float4*)&Qs[r * AP + c0 + i * 4] = v;
        }
    }

    float o[8][4];
#pragma unroll
    for (int nt = 0; nt < 8; nt++)
#pragma unroll
        for (int r = 0; r < 4; r++) o[nt][r] = 0.f;
    float l0 = 0.f, l1 = 0.f;

    const int row0 = qs + wid * 16 + g;   // this thread's even row
    const int qrow = wid * 16 + g;        // local

    const int t_lo = (qs > 255) ? ((qs - 255) >> 6) : 0;
    const int extra = (t_lo > 0) ? 1 : 0;
    const int ntiles = (qt - t_lo + 1) + extra;

    for (int it = 0; it < ntiles; it++) {
        const int kt = (extra && it == 0) ? 0 : (t_lo + it - extra);
        const int ks = kt << 6;
        __syncthreads();
        // stage K (tf32) and V transposed (tf32)
        {
            const int r = tid >> 1, c0 = (tid & 1) << 5;
            const float* ksrc = Kg + (size_t)(ks + r) * DH_ + c0;
            const float* vsrc = Vg + (size_t)(ks + r) * DH_ + c0;
#pragma unroll
            for (int i = 0; i < 8; i++) {
                float4 v = *(const float4*)(ksrc + i * 4);
                v.x = to_tf32(v.x); v.y = to_tf32(v.y);
                v.z = to_tf32(v.z); v.w = to_tf32(v.w);
                *(float4*)&Ks[r * AP + c0 + i * 4] = v;
                float4 w = *(const float4*)(vsrc + i * 4);
                const int d = c0 + i * 4;
                Vt[(d + 0) * AP + r] = to_tf32(w.x);
                Vt[(d + 1) * AP + r] = to_tf32(w.y);
                Vt[(d + 2) * AP + r] = to_tf32(w.z);
                Vt[(d + 3) * AP + r] = to_tf32(w.w);
            }
        }
        __syncthreads();

        // S = Q K^T
        float c[8][4];
#pragma unroll
        for (int nt = 0; nt < 8; nt++)
#pragma unroll
            for (int r = 0; r < 4; r++) c[nt][r] = 0.f;

        const uint32_t* Q32 = (const uint32_t*)Qs;
        const uint32_t* K32 = (const uint32_t*)Ks;
#pragma unroll
        for (int kk = 0; kk < 8; kk++) {
            const int kb = kk << 3;
            uint32_t a0 = Q32[qrow * AP + kb + tg];
            uint32_t a1 = Q32[(qrow + 8) * AP + kb + tg];
            uint32_t a2 = Q32[qrow * AP + kb + tg + 4];
            uint32_t a3 = Q32[(qrow + 8) * AP + kb + tg + 4];
#pragma unroll
            for (int nt = 0; nt < 8; nt++) {
                uint32_t b0 = K32[(nt * 8 + g) * AP + kb + tg];
                uint32_t b1 = K32[(nt * 8 + g) * AP + kb + tg + 4];
                MMA_TF32(c[nt][0], c[nt][1], c[nt][2], c[nt][3], a0, a1, a2, a3, b0, b1);
            }
        }

        // softcap + exp (polynomial) + mask; accumulate l; write P
#pragma unroll
        for (int nt = 0; nt < 8; nt++) {
            float p[4];
#pragma unroll
            for (int i = 0; i < 4; i++) {
                const int key = ks + nt * 8 + (tg << 1) + (i & 1);
                const int row = row0 + ((i >> 1) << 3);
                const bool valid = (key <= row) && ((key > row - 256) || (key < 4));
                float t = c[nt][i] * 0.125f;
                float u = t - t * t * t * 1.4814815e-3f;
                float e = fmaf(u, 0.041666668f, 0.16666667f);
                e = fmaf(u, e, 0.5f);
                e = fmaf(u, e, 1.0f);
                e = fmaf(u, e, 1.0f);
                p[i] = valid ? to_tf32(e) : 0.f;
            }
            l0 += p[0] + p[1];
            l1 += p[2] + p[3];
            *(float2*)&Ps[qrow * AP + nt * 8 + (tg << 1)]       = make_float2(p[0], p[1]);
            *(float2*)&Ps[(qrow + 8) * AP + nt * 8 + (tg << 1)] = make_float2(p[2], p[3]);
        }
        __syncwarp();   // each warp reads only its own 16 Ps rows

        // O += P V
        const uint32_t* P32 = (const uint32_t*)Ps;
        const uint32_t* V32 = (const uint32_t*)Vt;
#pragma unroll
        for (int kk = 0; kk < 8; kk++) {
            const int kb = kk << 3;
            uint32_t a0 = P32[qrow * AP + kb + tg];
            uint32_t a1 = P32[(qrow + 8) * AP + kb + tg];
            uint32_t a2 = P32[qrow * AP + kb + tg + 4];
            uint32_t a3 = P32[(qrow + 8) * AP + kb + tg + 4];
#pragma unroll
            for (int nt = 0; nt < 8; nt++) {
                uint32_t b0 = V32[(nt * 8 + g) * AP + kb + tg];
                uint32_t b1 = V32[(nt * 8 + g) * AP + kb + tg + 4];
                MMA_TF32(o[nt][0], o[nt][1], o[nt][2], o[nt][3], a0, a1, a2, a3, b0, b1);
            }
        }
    }

    // normalize + write ctx
    l0 += __shfl_xor_sync(0xffffffffu, l0, 1);
    l0 += __shfl_xor_sync(0xffffffffu, l0, 2);
    l1 += __shfl_xor_sync(0xffffffffu, l1, 1);
    l1 += __shfl_xor_sync(0xffffffffu, l1, 2);
    const float inv0 = 1.0f / l0, inv1 = 1.0f / l1;

    float* ctx0 = g_ctx + (size_t)(b * S_ + row0) * 1024 + h * 64;
    float* ctx1 = ctx0 + (size_t)8 * 1024;
#pragma unroll
    for (int nt = 0; nt < 8; nt++) {
        const int d = nt * 8 + (tg << 1);
        *(float2*)(ctx0 + d) = make_float2(o[nt][0] * inv0, o[nt][1] * inv0);
        *(float2*)(ctx1 + d) = make_float2(o[nt][2] * inv1, o[nt][3] * inv1);
    }
}

// ---------------- launch -----------------------------------------------------
extern "C" void kernel_launch(void* const* d_in, const int* in_sizes, int n_in,
                              void* d_out, int out_size)
{
    const float* x    = (const float*)d_in[0];
    const float* cosb = (const float*)d_in[1];
    const float* sinb = (const float*)d_in[2];
    const float* Wq   = (const float*)d_in[4];
    const float* Wk   = (const float*)d_in[5];
    const float* Wv   = (const float*)d_in[6];
    const float* Wo   = (const float*)d_in[7];
    float* out = (float*)d_out;

    float *qkv, *ctx, *wqkvT, *woT;
    cudaGetSymbolAddress((void**)&qkv,   g_qkv);
    cudaGetSymbolAddress((void**)&ctx,   g_ctx);
    cudaGetSymbolAddress((void**)&wqkvT, g_WqkvT);
    cudaGetSymbolAddress((void**)&woT,   g_WoT);

    wtrans<<<dim3(32, 32), dim3(32, 8)>>>(Wq, wqkvT,                       1024, 1024);
    wtrans<<<dim3(8,  32), dim3(32, 8)>>>(Wk, wqkvT + (size_t)1024 * 1024, 1024, 256);
    wtrans<<<dim3(8,  32), dim3(32, 8)>>>(Wv, wqkvT + (size_t)1280 * 1024, 1024, 256);
    wtrans<<<dim3(32, 32), dim3(32, 8)>>>(Wo, woT,                         1024, 1024);

    tgemm<<<dim3(12, 32), 256>>>(x, wqkvT, qkv, 1536, 1024);

    normrope_kernel<<<(M_ * 24) / 8, 256>>>(cosb, sinb);

    const int asmem = 4 * 64 * AP * (int)sizeof(float);
    cudaFuncSetAttribute(attn_kernel, cudaFuncAttributeMaxDynamicSharedMemorySize, asmem);
    attn_kernel<<<dim3(S_ / 64, NH_, B_), 128, asmem>>>();

    tgemm<<<dim3(8, 32), 256>>>(ctx, woT, out, 1024, 1024);
}